// round 13
// baseline (speedup 1.0000x reference)
#include <cuda_runtime.h>
#include <cuda_fp16.h>
#include <cstdint>
#include <math.h>

#define TB   64
#define NT   128
#define NPAIR 5

// fused weight tile layout (halves): per kp: net0(41984) net1(41984) net2(58368)
#define NETSZ 41984
#define KPSTR 142336
__device__ __half g_wtile[711680];
__device__ __half g_stile[16777216];   // 1024 blk x 4 chunks x 4096
__device__ __half g_atile[8388608];    // 1024 blk x 2 chunks x 4096

// smem byte offsets
#define XA_B  0u       // 2 x 8192
#define WT_B  16384u   // 2 x 16384
#define H_B   49152u   // 2 x 8192 (h for k0 / k1)
#define W3_B  65536u   // 2048
#define BS_B  67584u   // 1024 (256 floats: bs1[128] bs2[128])
#define OB_B  68608u   // 64 x 18 floats = 4608
#define SMEMB 73216u   // -> 3 CTAs/SM

__device__ __forceinline__ float sigf(float x) { return 1.0f / (1.0f + __expf(-x)); }
__device__ __forceinline__ uint32_t smem_u32(const void* p) {
    uint32_t a;
    asm("{ .reg .u64 t; cvta.to.shared.u64 t, %1; cvt.u32.u64 %0, t; }" : "=r"(a) : "l"(p));
    return a;
}
#define CPA16(dst, src) \
    asm volatile("cp.async.ca.shared.global [%0], [%1], 16;" :: "r"(dst), "l"(src))
#define CPA_COMMIT() asm volatile("cp.async.commit_group;" ::: "memory")
#define CPA_WAIT0()  asm volatile("cp.async.wait_group 0;" ::: "memory")

__device__ __forceinline__ void mma16(float c[4], uint32_t a0, uint32_t a1,
                                      uint32_t a2, uint32_t a3, uint32_t b0, uint32_t b1) {
    asm volatile("mma.sync.aligned.m16n8k16.row.col.f32.f16.f16.f32 "
                 "{%0,%1,%2,%3}, {%4,%5,%6,%7}, {%8,%9}, {%0,%1,%2,%3};"
                 : "+f"(c[0]), "+f"(c[1]), "+f"(c[2]), "+f"(c[3])
                 : "r"(a0), "r"(a1), "r"(a2), "r"(a3), "r"(b0), "r"(b1));
}

// ---------------- prep kernels ----------------
// k-permute within 16-group: half2 index pp -> col offset 2*(pp>>1) + 8*(pp&1)
__global__ void prep_x(const float* __restrict__ states, const float* __restrict__ actions) {
    int b = blockIdx.x;
    const float* ss = states + (size_t)b * 64 * 256;
    __half2* sd = reinterpret_cast<__half2*>(g_stile + ((size_t)b << 14));
    for (int i = threadIdx.x; i < 8192; i += 256) {
        int j = i >> 11, rem = i & 2047;
        int q = rem >> 9, rr = rem & 511, r = rr >> 3, pp = rr & 7;
        int c = (j << 6) + (q << 4) + ((pp >> 1) << 1) + ((pp & 1) << 3);
        sd[i] = __floats2half2_rn(ss[r * 256 + c], ss[r * 256 + c + 1]);
    }
    const float* as = actions + (size_t)b * 64 * 128;
    __half2* ad = reinterpret_cast<__half2*>(g_atile + ((size_t)b << 13));
    for (int i = threadIdx.x; i < 4096; i += 256) {
        int j = i >> 11, rem = i & 2047;
        int q = rem >> 9, rr = rem & 511, r = rr >> 3, pp = rr & 7;
        int c = (j << 6) + (q << 4) + ((pp >> 1) << 1) + ((pp & 1) << 3);
        ad[i] = __floats2half2_rn(as[r * 128 + c], as[r * 128 + c + 1]);
    }
}

__global__ void prep_w(const float* __restrict__ kW1, const float* __restrict__ kW2,
                       const float* __restrict__ kW3,
                       const float* __restrict__ aW1, const float* __restrict__ aW2,
                       const float* __restrict__ aW3,
                       const float* __restrict__ cW1, const float* __restrict__ cW2,
                       const float* __restrict__ cW3)
{
    int kp = blockIdx.x / 3, net = blockIdx.x % 3;
    const float* W1 = (net == 0) ? kW1 : ((net == 1) ? aW1 : cW1);
    const float* W2 = (net == 0) ? kW2 : ((net == 1) ? aW2 : cW2);
    const float* W3 = (net == 0) ? kW3 : ((net == 1) ? aW3 : cW3);
    const int IN = (net == 2) ? 384 : 256;
    const int NCH = (net == 2) ? 6 : 4;
    __half2* dst = reinterpret_cast<__half2*>(
        g_wtile + (size_t)kp * KPSTR + (size_t)net * NETSZ);

    // L1: NCH chunks, each [4q][128n][16k]; n<64 -> kernel 2kp, n>=64 -> 2kp+1
    int n1 = NCH * 4096;
    for (int i = threadIdx.x; i < n1; i += blockDim.x) {
        int j = i >> 12, rem = i & 4095;
        int q = rem >> 10, rr = rem & 1023, n = rr >> 3, pp = rr & 7;
        int c = (j << 6) + (q << 4) + ((pp >> 1) << 1) + ((pp & 1) << 3);
        int k = 2 * kp + (n >> 6), o = n & 63;
        const float* s = W1 + ((size_t)k * 64 + o) * IN + c;
        dst[i] = __floats2half2_rn(s[0], s[1]);
    }
    // L2 chunk
    __half2* d2 = dst + n1;
    for (int i = threadIdx.x; i < 4096; i += blockDim.x) {
        int q = i >> 10, rr = i & 1023, n = rr >> 3, pp = rr & 7;
        int c = (q << 4) + ((pp >> 1) << 1) + ((pp & 1) << 3);
        int k = 2 * kp + (n >> 6), o = n & 63;
        const float* s = W2 + ((size_t)k * 64 + o) * 64 + c;
        d2[i] = __floats2half2_rn(s[0], s[1]);
    }
    // L3 tile [4q][16n][16]; n<8 -> k0 outs, n>=8 -> k1 outs
    __half2* d3 = d2 + 4096;
    for (int i = threadIdx.x; i < 512; i += blockDim.x) {
        int q = i >> 7, rr = i & 127, n = rr >> 3, pp = rr & 7;
        int c = (q << 4) + ((pp >> 1) << 1) + ((pp & 1) << 3);
        int k = 2 * kp + (n >> 3), o = n & 7;
        float v0, v1;
        if (net == 0) { v0 = (o == 0) ? W3[(size_t)k * 64 + c] : 0.f;
                        v1 = (o == 0) ? W3[(size_t)k * 64 + c + 1] : 0.f; }
        else          { v0 = W3[((size_t)k * 8 + o) * 64 + c];
                        v1 = W3[((size_t)k * 8 + o) * 64 + c + 1]; }
        d3[i] = __floats2half2_rn(v0, v1);
    }
}

// ---------------- main ----------------
__device__ __forceinline__ void cp_w(uint32_t dstb, const __half* __restrict__ src, int tid) {
    #pragma unroll
    for (int q = 0; q < 8; q++) {
        int f = tid + 128 * q;
        CPA16(dstb + (uint32_t)(f << 4), src + (f << 3));
    }
}
__device__ __forceinline__ void cp_x(uint32_t dstb, const __half* __restrict__ src, int tid) {
    #pragma unroll
    for (int q = 0; q < 4; q++) {
        int f = tid + 128 * q;
        CPA16(dstb + (uint32_t)(f << 4), src + (f << 3));
    }
}

// warp m32 x n64 over one k64 chunk. A: [4q][64r][16], B: [4q][128n][16]
__device__ __forceinline__ void mma_chunk(const __half* __restrict__ A,
                                          const __half* __restrict__ B,
                                          float acc[2][8][4], int wbase, int nc0, int g, int t) {
    #pragma unroll
    for (int q = 0; q < 4; q++) {
        const __half* aq = A + (q << 10);
        const __half* bq = B + (q << 11);
        uint2 A00 = *reinterpret_cast<const uint2*>(aq + ((wbase + g) << 4) + 4 * t);
        uint2 A01 = *reinterpret_cast<const uint2*>(aq + ((wbase + g + 8) << 4) + 4 * t);
        uint2 A10 = *reinterpret_cast<const uint2*>(aq + ((wbase + g + 16) << 4) + 4 * t);
        uint2 A11 = *reinterpret_cast<const uint2*>(aq + ((wbase + g + 24) << 4) + 4 * t);
        #pragma unroll
        for (int nt = 0; nt < 8; nt++) {
            uint2 Bv = *reinterpret_cast<const uint2*>(bq + ((nc0 + nt * 8 + g) << 4) + 4 * t);
            mma16(acc[0][nt], A00.x, A01.x, A00.y, A01.y, Bv.x, Bv.y);
            mma16(acc[1][nt], A10.x, A11.x, A10.y, A11.y, Bv.x, Bv.y);
        }
    }
}
__device__ __forceinline__ void zacc(float acc[2][8][4]) {
    #pragma unroll
    for (int m = 0; m < 2; m++)
        #pragma unroll
        for (int n = 0; n < 8; n++)
            #pragma unroll
            for (int i = 0; i < 4; i++) acc[m][n][i] = 0.0f;
}
// bias+relu into warp-own h slice (h_nh, cols local 0..63, rows wbase..wbase+31)
__device__ __forceinline__ void epi_h(const float acc[2][8][4], __half* __restrict__ hn,
                                      const float* __restrict__ bias,
                                      int wbase, int nc0, int g, int t) {
    #pragma unroll
    for (int nt = 0; nt < 8; nt++) {
        int cl = nt * 8 + 2 * t;               // local col in h
        int q = nt >> 1;
        int po = 4 * t + 2 * (nt & 1);
        float b0 = bias[nc0 + cl], b1 = bias[nc0 + cl + 1];
        #pragma unroll
        for (int mt = 0; mt < 2; mt++) {
            int r0 = wbase + 16 * mt + g;
            __half2 v0 = __floats2half2_rn(fmaxf(acc[mt][nt][0] + b0, 0.f),
                                           fmaxf(acc[mt][nt][1] + b1, 0.f));
            __half2 v1 = __floats2half2_rn(fmaxf(acc[mt][nt][2] + b0, 0.f),
                                           fmaxf(acc[mt][nt][3] + b1, 0.f));
            *reinterpret_cast<__half2*>(hn + (q << 10) + (r0 << 4) + po) = v0;
            *reinterpret_cast<__half2*>(hn + (q << 10) + ((r0 + 8) << 4) + po) = v1;
        }
    }
}

__global__ void __launch_bounds__(NT, 3)
qplex_kp_kernel(
    const float* __restrict__ kb1, const float* __restrict__ kb2, const float* __restrict__ kb3,
    const float* __restrict__ ab1, const float* __restrict__ ab2, const float* __restrict__ ab3,
    const float* __restrict__ cb1, const float* __restrict__ cb2, const float* __restrict__ cb3,
    float* __restrict__ out)
{
    extern __shared__ char smc[];
    __half* h   = reinterpret_cast<__half*>(smc + H_B);
    __half* w3t = reinterpret_cast<__half*>(smc + W3_B);
    float* bs   = reinterpret_cast<float*>(smc + BS_B);
    float* ob   = reinterpret_cast<float*>(smc + OB_B);
    const uint32_t smb = smem_u32(smc);

    const int tid = threadIdx.x, lane = tid & 31;
    const int g = lane >> 2, t = lane & 3;
    const int wid = tid >> 5, nh = wid >> 1, rg = wid & 1;
    const int wbase = rg << 5, nc0 = nh << 6;
    const int blk = blockIdx.x;

    const float* B1s[3] = {kb1, ab1, cb1};
    const float* B2s[3] = {kb2, ab2, cb2};
    const __half* xt = g_stile + ((size_t)blk << 14);
    const __half* at = g_atile + ((size_t)blk << 13);
    __half* xaf[2] = {reinterpret_cast<__half*>(smc + XA_B),
                      reinterpret_cast<__half*>(smc + XA_B + 8192)};
    __half* wtf[2] = {reinterpret_cast<__half*>(smc + WT_B),
                      reinterpret_cast<__half*>(smc + WT_B + 16384)};
    const uint32_t xab[2] = {smb + XA_B, smb + XA_B + 8192};
    const uint32_t wtb[2] = {smb + WT_B, smb + WT_B + 16384};
    const uint32_t w3b = smb + W3_B;

    float acc[2][8][4], keyr[2], agr[2][8], accr[8];
    #pragma unroll
    for (int o = 0; o < 8; o++) accr[o] = 0.f;

    // kernel prologue: chunk0 of (kp0,net0)
    const __half* wnet = g_wtile;
    cp_w(wtb[0], wnet, tid);
    cp_x(xab[0], xt, tid);
    CPA_COMMIT();
    int p0 = 0;

    for (int it = 0; it < 15; it++) {
        const int net = it - 3 * (it / 3) , kp = it / 3;
        const int NCH = (net == 2) ? 6 : 4;
        const __half* w2s = wnet + (size_t)NCH * 8192;
        const __half* w3s = w2s + 8192;
        const __half* wnext = wnet + ((net == 2) ? 58368 : 41984);

        zacc(acc);
        // ---- layer 1: NCH fused N=128 chunks ----
        for (int j = 0; j < NCH; j++) {
            CPA_WAIT0();
            __syncthreads();
            if (j == 0) {   // biases (race-safe: after barrier)
                int k = 2 * kp + (tid >> 6), o = tid & 63;
                bs[tid]       = __ldg(B1s[net] + k * 64 + o);
                bs[128 + tid] = __ldg(B2s[net] + k * 64 + o);
            }
            if (j + 1 < NCH) {
                const __half* xsrc = (j + 1 < 4) ? xt + ((j + 1) << 12)
                                                 : at + ((j - 3) << 12);
                cp_w(wtb[(p0 + j + 1) & 1], wnet + ((size_t)(j + 1) << 13), tid);
                cp_x(xab[(p0 + j + 1) & 1], xsrc, tid);
            } else {
                cp_w(wtb[(p0 + NCH) & 1], w2s, tid);
                CPA16(w3b + (uint32_t)(tid << 4), w3s + (tid << 3));
            }
            CPA_COMMIT();
            mma_chunk(xaf[(p0 + j) & 1], wtf[(p0 + j) & 1], acc, wbase, nc0, g, t);
        }
        epi_h(acc, h + (nh << 12), bs, wbase, nc0, g, t);
        zacc(acc);
        __syncwarp();

        // ---- layer 2 (A = own h_nh) ----
        CPA_WAIT0();
        __syncthreads();
        if (it < 14) {           // pipeline next (kp,net) chunk0
            cp_w(wtb[(p0 + NCH + 1) & 1], wnext, tid);
            cp_x(xab[(p0 + NCH + 1) & 1], xt, tid);
        }
        CPA_COMMIT();
        mma_chunk(h + (nh << 12), wtf[(p0 + NCH) & 1], acc, wbase, nc0, g, t);
        __syncwarp();
        epi_h(acc, h + (nh << 12), bs + 128, wbase, 0, g, t);
        __syncwarp();

        // ---- layer 3: m32 x n8 per warp (warp nh -> kernel nh outputs) ----
        {
            float a3[2][4];
            #pragma unroll
            for (int m = 0; m < 2; m++)
                #pragma unroll
                for (int i = 0; i < 4; i++) a3[m][i] = 0.f;
            const __half* hn = h + (nh << 12);
            #pragma unroll
            for (int q = 0; q < 4; q++) {
                const __half* aq = hn + (q << 10);
                uint2 A00 = *reinterpret_cast<const uint2*>(aq + ((wbase + g) << 4) + 4 * t);
                uint2 A01 = *reinterpret_cast<const uint2*>(aq + ((wbase + g + 8) << 4) + 4 * t);
                uint2 A10 = *reinterpret_cast<const uint2*>(aq + ((wbase + g + 16) << 4) + 4 * t);
                uint2 A11 = *reinterpret_cast<const uint2*>(aq + ((wbase + g + 24) << 4) + 4 * t);
                uint2 Bv = *reinterpret_cast<const uint2*>(w3t + (q << 8) + ((nh * 8 + g) << 4) + 4 * t);
                mma16(a3[0], A00.x, A01.x, A00.y, A01.y, Bv.x, Bv.y);
                mma16(a3[1], A10.x, A11.x, A10.y, A11.y, Bv.x, Bv.y);
            }
            #pragma unroll
            for (int mt = 0; mt < 2; mt++) {
                int r0 = wbase + 16 * mt + g;
                *reinterpret_cast<float2*>(ob + r0 * 18 + nh * 8 + 2 * t)       = make_float2(a3[mt][0], a3[mt][1]);
                *reinterpret_cast<float2*>(ob + (r0 + 8) * 18 + nh * 8 + 2 * t) = make_float2(a3[mt][2], a3[mt][3]);
            }
        }
        __syncthreads();
        // ---- scalar combine (both kernels of the pair) ----
        if (tid < 64) {
            const float* orow = ob + tid * 18;
            if (net == 0) {
                #pragma unroll
                for (int kk = 0; kk < 2; kk++)
                    keyr[kk] = fabsf(orow[kk * 8] + __ldg(kb3 + 2 * kp + kk)) + 1e-10f;
            } else if (net == 1) {
                #pragma unroll
                for (int kk = 0; kk < 2; kk++)
                    #pragma unroll
                    for (int o = 0; o < 8; o++)
                        agr[kk][o] = sigf(orow[kk * 8 + o] + __ldg(ab3 + (2 * kp + kk) * 8 + o));
            } else {
                #pragma unroll
                for (int kk = 0; kk < 2; kk++)
                    #pragma unroll
                    for (int o = 0; o < 8; o++)
                        accr[o] += keyr[kk] * agr[kk][o] *
                                   sigf(orow[kk * 8 + o] + __ldg(cb3 + (2 * kp + kk) * 8 + o));
            }
        }
        wnet = wnext;
        p0 = (p0 + NCH + 1) & 1;
    }

    if (tid < 64) {
        float4* op = reinterpret_cast<float4*>(out + (size_t)(blk * TB + tid) * 8);
        op[0] = make_float4(accr[0], accr[1], accr[2], accr[3]);
        op[1] = make_float4(accr[4], accr[5], accr[6], accr[7]);
    }
}

extern "C" void kernel_launch(void* const* d_in, const int* in_sizes, int n_in,
                              void* d_out, int out_size)
{
    const float* states  = (const float*)d_in[0];
    const float* actions = (const float*)d_in[1];
    const float* kW1 = (const float*)d_in[2];  const float* kb1 = (const float*)d_in[3];
    const float* kW2 = (const float*)d_in[4];  const float* kb2 = (const float*)d_in[5];
    const float* kW3 = (const float*)d_in[6];  const float* kb3 = (const float*)d_in[7];
    const float* aW1 = (const float*)d_in[8];  const float* ab1 = (const float*)d_in[9];
    const float* aW2 = (const float*)d_in[10]; const float* ab2 = (const float*)d_in[11];
    const float* aW3 = (const float*)d_in[12]; const float* ab3 = (const float*)d_in[13];
    const float* cW1 = (const float*)d_in[14]; const float* cb1 = (const float*)d_in[15];
    const float* cW2 = (const float*)d_in[16]; const float* cb2 = (const float*)d_in[17];
    const float* cW3 = (const float*)d_in[18]; const float* cb3 = (const float*)d_in[19];
    float* out = (float*)d_out;

    prep_w<<<15, 256>>>(kW1, kW2, kW3, aW1, aW2, aW3, cW1, cW2, cW3);
    prep_x<<<1024, 256>>>(states, actions);

    cudaFuncSetAttribute(qplex_kp_kernel,
                         cudaFuncAttributeMaxDynamicSharedMemorySize, (int)SMEMB);
    qplex_kp_kernel<<<1024, NT, SMEMB>>>(
        kb1, kb2, kb3, ab1, ab2, ab3, cb1, cb2, cb3, out);
}